// round 6
// baseline (speedup 1.0000x reference)
#include <cuda_runtime.h>
#include <math.h>

// Problem constants (fixed by the dataset)
#define NN   50000
#define EE   1600000
#define ETOT (EE + NN)   // edges + self-loops
#define GG   512
#define HC   32          // H*C

// ---------------- scratch (device globals; no allocation allowed) ----------
__device__ __align__(16) float g_deg  [NN];
__device__ __align__(16) float g_x0   [NN * 3];
__device__ __align__(16) float g_xcur [NN * HC];
__device__ __align__(16) float g_xl   [NN * HC];
__device__ __align__(16) float g_xr   [NN * HC];
__device__ __align__(16) float g_out  [NN * HC];
__device__ __align__(16) float g_score[ETOT * 2];
__device__ int                 g_count[NN];
__device__ int                 g_off  [NN + 1];
__device__ int                 g_cursor[NN];
__device__ int                 g_csr_src[ETOT];
__device__ __align__(16) float g_sums [GG * HC];
__device__ __align__(16) float g_cnt  [GG];

static inline int div_up(int a, int b) { return (a + b - 1) / b; }

__device__ __forceinline__ void red4(float* p, float4 v) {
    asm volatile("red.global.add.v4.f32 [%0], {%1,%2,%3,%4};"
                 :: "l"(p), "f"(v.x), "f"(v.y), "f"(v.z), "f"(v.w) : "memory");
}

// ---------------- prep kernels ----------------------------------------------

__global__ void k_zero() {
    int i = blockIdx.x * blockDim.x + threadIdx.x;
    if (i < NN) { g_deg[i] = 0.f; g_count[i] = 1; }   // 1 = self-loop
}

// degree feature (src+dst over original edges) + in-degree histogram (dst only)
__global__ void k_deghist(const int* __restrict__ ei) {
    int e = blockIdx.x * blockDim.x + threadIdx.x;
    if (e < EE) {
        int s = ei[e], d = ei[EE + e];
        atomicAdd(&g_deg[s], 1.f);
        atomicAdd(&g_deg[d], 1.f);
        atomicAdd(&g_count[d], 1);
    }
}

// single-block exclusive scan of g_count -> g_off / g_cursor
__global__ void k_scan() {
    __shared__ int sh[1024];
    int t = threadIdx.x;
    const int chunk = (NN + 1023) / 1024;
    int b = t * chunk, e = min(b + chunk, NN);
    int sum = 0;
    for (int i = b; i < e; i++) sum += g_count[i];
    sh[t] = sum;
    __syncthreads();
    for (int off = 1; off < 1024; off <<= 1) {
        int v = (t >= off) ? sh[t - off] : 0;
        __syncthreads();
        sh[t] += v;
        __syncthreads();
    }
    int run = (t > 0) ? sh[t - 1] : 0;
    for (int i = b; i < e; i++) {
        g_off[i] = run; g_cursor[i] = run;
        run += g_count[i];
    }
    if (t == 0) g_off[NN] = ETOT;
}

// scatter src indices into CSR (edges then self-loops)
__global__ void k_scatter(const int* __restrict__ ei) {
    int i = blockIdx.x * blockDim.x + threadIdx.x;
    if (i < EE) {
        int d = ei[EE + i];
        int p = atomicAdd(&g_cursor[d], 1);
        g_csr_src[p] = ei[i];
    } else if (i < ETOT) {
        int n = i - EE;
        int p = atomicAdd(&g_cursor[n], 1);
        g_csr_src[p] = n;
    }
}

__global__ void k_feat(const float* __restrict__ rf) {
    int n = blockIdx.x * blockDim.x + threadIdx.x;
    if (n < NN) {
        g_x0[n * 3 + 0] = 1.f;
        g_x0[n * 3 + 1] = g_deg[n];
        g_x0[n * 3 + 2] = rf[n];
    }
}

// xl = x @ Wl^T + bl ; xr = x @ Wr^T + br.  One thread per (node, out-chan).
template <int F>
__global__ void k_lin(const float* __restrict__ Wl, const float* __restrict__ bl,
                      const float* __restrict__ Wr, const float* __restrict__ br) {
    int t = blockIdx.x * blockDim.x + threadIdx.x;
    if (t >= NN * HC) return;
    int n = t >> 5, o = t & 31;
    const float* x = (F == 3) ? (g_x0 + n * 3) : (g_xcur + n * HC);
    float al = bl[o], ar = br[o];
#pragma unroll
    for (int k = 0; k < F; k++) {
        float xv = x[k];
        al += Wl[o * F + k] * xv;
        ar += Wr[o * F + k] * xv;
    }
    g_xl[t] = al;
    g_xr[t] = ar;
}

// ---------------- fused conv: warp per destination node ---------------------
// lane = channel (0..31), head = lane>>4.  No atomics anywhere.

__device__ __forceinline__ float hreduce16(float v) {
    v += __shfl_xor_sync(0xffffffffu, v, 8);
    v += __shfl_xor_sync(0xffffffffu, v, 4);
    v += __shfl_xor_sync(0xffffffffu, v, 2);
    v += __shfl_xor_sync(0xffffffffu, v, 1);
    return v;   // lanes 0-15: head0 sum, lanes 16-31: head1 sum
}

__global__ void __launch_bounds__(256) k_conv(const float* __restrict__ att,
                                              const float* __restrict__ bias,
                                              int dst_sel) {
    int w = (blockIdx.x * blockDim.x + threadIdx.x) >> 5;
    if (w >= NN) return;
    int lane = threadIdx.x & 31;
    int h = lane >> 4;
    int beg = g_off[w], end = g_off[w + 1];
    float xr   = g_xr[w * HC + lane];
    float attv = att[lane];
    float mx = -3.0e38f;

    // ---- pass 1: scores + per-head max (scores cached in g_score) ----
    int i = beg;
    for (; i + 4 <= end; i += 4) {
        int s0 = g_csr_src[i],     s1 = g_csr_src[i + 1];
        int s2 = g_csr_src[i + 2], s3 = g_csr_src[i + 3];
        float a0 = g_xl[s0 * HC + lane], a1 = g_xl[s1 * HC + lane];
        float a2 = g_xl[s2 * HC + lane], a3 = g_xl[s3 * HC + lane];
        float m0 = a0 + xr, m1 = a1 + xr, m2 = a2 + xr, m3 = a3 + xr;
        m0 = (m0 > 0.f) ? m0 : 0.2f * m0;
        m1 = (m1 > 0.f) ? m1 : 0.2f * m1;
        m2 = (m2 > 0.f) ? m2 : 0.2f * m2;
        m3 = (m3 > 0.f) ? m3 : 0.2f * m3;
        float v0 = hreduce16(m0 * attv);
        float v1 = hreduce16(m1 * attv);
        float v2 = hreduce16(m2 * attv);
        float v3 = hreduce16(m3 * attv);
        if ((lane & 15) == 0) {
            g_score[(i    ) * 2 + h] = v0;
            g_score[(i + 1) * 2 + h] = v1;
            g_score[(i + 2) * 2 + h] = v2;
            g_score[(i + 3) * 2 + h] = v3;
        }
        mx = fmaxf(mx, fmaxf(fmaxf(v0, v1), fmaxf(v2, v3)));
    }
    for (; i < end; i++) {
        int s = g_csr_src[i];
        float m = g_xl[s * HC + lane] + xr;
        m = (m > 0.f) ? m : 0.2f * m;
        float v = hreduce16(m * attv);
        if ((lane & 15) == 0) g_score[i * 2 + h] = v;
        mx = fmaxf(mx, v);
    }

    // ---- pass 2: exp, denom, weighted aggregate (registers only) ----
    float acc = 0.f, den = 0.f;
    i = beg;
    for (; i + 4 <= end; i += 4) {
        int s0 = g_csr_src[i],     s1 = g_csr_src[i + 1];
        int s2 = g_csr_src[i + 2], s3 = g_csr_src[i + 3];
        float e0 = __expf(g_score[(i    ) * 2 + h] - mx);
        float e1 = __expf(g_score[(i + 1) * 2 + h] - mx);
        float e2 = __expf(g_score[(i + 2) * 2 + h] - mx);
        float e3 = __expf(g_score[(i + 3) * 2 + h] - mx);
        float a0 = g_xl[s0 * HC + lane], a1 = g_xl[s1 * HC + lane];
        float a2 = g_xl[s2 * HC + lane], a3 = g_xl[s3 * HC + lane];
        den += (e0 + e1) + (e2 + e3);
        acc += a0 * e0 + a1 * e1 + a2 * e2 + a3 * e3;
    }
    for (; i < end; i++) {
        int s = g_csr_src[i];
        float ex = __expf(g_score[i * 2 + h] - mx);
        den += ex;
        acc += g_xl[s * HC + lane] * ex;
    }

    float v = acc / (den + 1e-16f) + bias[lane];
    v = (v > 0.f) ? v : expm1f(v);
    if (dst_sel == 0) g_xcur[w * HC + lane] = v;
    else              g_out [w * HC + lane] = v;
}

// ---------------- pool + head ------------------------------------------------

__global__ void k_zero_pool() {
    int i = blockIdx.x * blockDim.x + threadIdx.x;
    if (i < GG * HC) g_sums[i] = 0.f;
    if (i < GG)      g_cnt[i]  = 0.f;
}

__global__ void k_pool4(const int* __restrict__ batch) {
    int t = blockIdx.x * blockDim.x + threadIdx.x;
    if (t >= NN * 8) return;
    int n = t >> 3, j = t & 7;
    int g = batch[n];
    const float4* out4 = (const float4*)g_out;
    red4(&g_sums[g * HC + 4 * j], out4[n * 8 + j]);
    if (j == 0) atomicAdd(&g_cnt[g], 1.f);
}

__global__ void k_head(const float* __restrict__ Wfc, const float* __restrict__ bfc,
                       float* __restrict__ out) {
    int g = blockIdx.x * blockDim.x + threadIdx.x;
    if (g >= GG) return;
    float inv = 1.f / fmaxf(g_cnt[g], 1.f);
    float l0 = bfc[0], l1 = bfc[1];
#pragma unroll
    for (int k = 0; k < HC; k++) {
        float p = g_sums[g * HC + k] * inv;
        l0 += Wfc[k] * p;
        l1 += Wfc[HC + k] * p;
    }
    float mx  = fmaxf(l0, l1);
    float lse = mx + logf(expf(l0 - mx) + expf(l1 - mx));
    out[g * 2 + 0] = l0 - lse;
    out[g * 2 + 1] = l1 - lse;
}

// ---------------- launch -----------------------------------------------------

extern "C" void kernel_launch(void* const* d_in, const int* in_sizes, int n_in,
                              void* d_out, int out_size) {
    const int* ei    = (const int*)d_in[0];
    const int* batch = (const int*)d_in[1];
    const float* rand_feat = (const float*)d_in[2];
    const float* W1l = (const float*)d_in[3];
    const float* b1l = (const float*)d_in[4];
    const float* W1r = (const float*)d_in[5];
    const float* b1r = (const float*)d_in[6];
    const float* att1 = (const float*)d_in[7];
    const float* bias1 = (const float*)d_in[8];
    const float* W2l = (const float*)d_in[9];
    const float* b2l = (const float*)d_in[10];
    const float* W2r = (const float*)d_in[11];
    const float* b2r = (const float*)d_in[12];
    const float* att2 = (const float*)d_in[13];
    const float* bias2 = (const float*)d_in[14];
    const float* Wfc = (const float*)d_in[15];
    const float* bfc = (const float*)d_in[16];
    float* out = (float*)d_out;

    const int B = 256;
    const int gNode   = div_up(NN, B);
    const int gEdge   = div_up(EE, B);
    const int gNodeHC = div_up(NN * HC, B);

    // prep: degree + CSR by destination
    k_zero<<<gNode, B>>>();
    k_deghist<<<gEdge, B>>>(ei);
    k_scan<<<1, 1024>>>();
    k_scatter<<<div_up(ETOT, B), B>>>(ei);
    k_feat<<<gNode, B>>>(rand_feat);

    // ---- conv1 ----
    k_lin<3><<<gNodeHC, B>>>(W1l, b1l, W1r, b1r);
    k_conv<<<gNodeHC, B>>>(att1, bias1, 0);   // -> g_xcur

    // ---- conv2 ----
    k_lin<32><<<gNodeHC, B>>>(W2l, b2l, W2r, b2r);
    k_conv<<<gNodeHC, B>>>(att2, bias2, 1);   // -> g_out

    // ---- pool + head ----
    k_zero_pool<<<div_up(GG * HC, B), B>>>();
    k_pool4<<<div_up(NN * 8, B), B>>>(batch);
    k_head<<<div_up(GG, B), B>>>(Wfc, bfc, out);
}